// round 9
// baseline (speedup 1.0000x reference)
#include <cuda_runtime.h>

#define CK __restrict__
typedef unsigned long long ull;

// ---------------- f32x2 helpers (packed fp32 pipe, sm_103a) ----------------
__device__ __forceinline__ ull pack2(float lo, float hi) {
    ull r; asm("mov.b64 %0, {%1, %2};" : "=l"(r) : "f"(lo), "f"(hi)); return r;
}
__device__ __forceinline__ void unpack2(ull v, float& lo, float& hi) {
    asm("mov.b64 {%0, %1}, %2;" : "=f"(lo), "=f"(hi) : "l"(v));
}
__device__ __forceinline__ void ffma2(ull& d, ull a, ull b) {
    asm("fma.rn.f32x2 %0, %1, %2, %0;" : "+l"(d) : "l"(a), "l"(b));
}
__device__ __forceinline__ ull mul2(ull a, ull b) {
    ull r; asm("mul.rn.f32x2 %0, %1, %2;" : "=l"(r) : "l"(a), "l"(b)); return r;
}
__device__ __forceinline__ ull add2(ull a, ull b) {
    ull r; asm("add.rn.f32x2 %0, %1, %2;" : "=l"(r) : "l"(a), "l"(b)); return r;
}

// ---------------- scratch (device globals: allocation-free) ----------------
__device__ float g_y [4*128*128*128];                 // deconv output (incl. bias)
__device__ float g_kf[4*9*128*128];                   // PAC gaussian factors
__device__ __align__(16) float g_w1d[4*256*128*4*2];  // w1 repacked+dup: [p][ci][co][tap][2]
__device__ __align__(16) float g_w2d[128*9*128*2];    // wk repacked+dup: [c][ij][o][2]

// ---------------- weight prep ----------------
__global__ void prep_weights_kernel(const float* CK w1, const float* CK w2) {
    int idx = blockIdx.x * blockDim.x + threadIdx.x;
    const int n1 = 4*256*128*4;
    if (idx < n1) {
        int t  = idx & 3;
        int co = (idx >> 2) & 127;
        int ci = (idx >> 9) & 255;
        int p  = idx >> 17;
        int pr = p >> 1, ps = p & 1;
        int th = t >> 1, tw = t & 1;
        int kh = 2*th + 1 - pr;
        int kw = 2*tw + 1 - ps;
        float v = w1[((ci*128 + co)*4 + kh)*4 + kw];
        g_w1d[idx*2]   = v;   // duplicated pair for f32x2 broadcast
        g_w1d[idx*2+1] = v;
    }
    const int n2 = 128*9*128;
    if (idx < n2) {
        int o  = idx & 127;
        int ij = (idx >> 7) % 9;
        int c  = idx / (9*128);
        int i = ij / 3, j = ij % 3;
        float v = w2[((c*128 + o)*3 + (2 - i))*3 + (2 - j)];  // wk[o,c,i,j]=w2[c,o,2-i,2-j]
        g_w2d[idx*2]   = v;
        g_w2d[idx*2+1] = v;
    }
}

// ---------------- stage 1: conv_transpose 4x4 s2 p1 (f32x2, LDS.128) ----------------
// Per parity class (pr,ps): effective 2x2 stride-1 conv on the 64x64 input.
// Block: 64 co x (8R x 32S). Thread: 8co x 8sp (4 f32x2 pairs).
// Two x copies (shift 0, shift 1), row stride 36 floats (144B = 9x16B, odd slot
// stride -> LDS.128 conflict-free with lane map r=pg&7).
static const int DC_X_STRIDE = 36;
static const int DC_XC_BYTES = 16*9*DC_X_STRIDE*4;   // 20736 per copy
static const int DC_SMEM     = 2*DC_XC_BYTES + 16*64*4*8;  // 41472 + 32768 = 74240

__global__ __launch_bounds__(256, 2)
void deconv_kernel(const float* CK x, const float* CK b1) {
    extern __shared__ unsigned char smem_raw[];
    float (*xs0)[9][DC_X_STRIDE] = (float(*)[9][DC_X_STRIDE])smem_raw;
    float (*xs1)[9][DC_X_STRIDE] = (float(*)[9][DC_X_STRIDE])(smem_raw + DC_XC_BYTES);
    ull   (*ws)[64][4]           = (ull(*)[64][4])(smem_raw + 2*DC_XC_BYTES);

    const int tid = threadIdx.x;
    const int rt = blockIdx.x >> 1;
    const int st = blockIdx.x & 1;
    const int R0 = rt * 8, S0 = st * 32;
    const int p   = blockIdx.y >> 1;
    const int co0 = (blockIdx.y & 1) * 64;
    const int pr = p >> 1, ps = p & 1;
    const int b = blockIdx.z;

    const int cg8 = tid >> 5;          // 8 co-groups of 8
    const int pg  = tid & 31;
    const int r   = pg & 7;            // 0..7 (phase-group friendly)
    const int s8  = (pg >> 3) * 8;     // 0,8,16,24

    ull acc[8][4];
#pragma unroll
    for (int a = 0; a < 8; a++)
#pragma unroll
        for (int q = 0; q < 4; q++) acc[a][q] = 0ull;

    const int rowbase = R0 - (1 - pr);
    const int colbase = S0 - (1 - ps);

    for (int ch = 0; ch < 16; ch++) {
        const int ci0 = ch * 16;
        // x halo tile (zero padded at border); dual store: shift0 + shift1
        for (int e = tid; e < 16*9*34; e += 256) {
            int col = e % 34;
            int tmp = e / 34;
            int row = tmp % 9;
            int cc  = tmp / 9;
            int gr = rowbase + row, gc = colbase + col;
            float v = 0.f;
            if ((unsigned)gr < 64u && (unsigned)gc < 64u)
                v = x[((b*256 + ci0 + cc)*64 + gr)*64 + gc];
            xs0[cc][row][col] = v;
            if (col >= 1) xs1[cc][row][col - 1] = v;
        }
        // duplicated weight pairs (contiguous 512-float rows per ci)
        {
            const ull* wsrc = (const ull*)&g_w1d[((size_t)(p*256 + ci0)*128 + co0)*8];
            ull* wdst = &ws[0][0][0];
            for (int e = tid; e < 16*256; e += 256) {
                int cc = e >> 8;
                int rest = e & 255;
                wdst[cc*256 + rest] = wsrc[cc*512 + rest];
            }
        }
        __syncthreads();

#pragma unroll 1
        for (int cc = 0; cc < 16; cc++) {
            const ulonglong2* ph0 = (const ulonglong2*)&xs0[cc][r + 1][s8];
            const ulonglong2* ph1 = (const ulonglong2*)&xs1[cc][r + 1][s8];
            const ulonglong2* pl0 = (const ulonglong2*)&xs0[cc][r    ][s8];
            const ulonglong2* pl1 = (const ulonglong2*)&xs1[cc][r    ][s8];
            ulonglong2 h0a = ph0[0], h0b = ph0[1];
            ulonglong2 h1a = ph1[0], h1b = ph1[1];
            ulonglong2 l0a = pl0[0], l0b = pl0[1];
            ulonglong2 l1a = pl1[0], l1b = pl1[1];
            ull xh0[4] = {h0a.x, h0a.y, h0b.x, h0b.y};
            ull xh1[4] = {h1a.x, h1a.y, h1b.x, h1b.y};
            ull xl0[4] = {l0a.x, l0a.y, l0b.x, l0b.y};
            ull xl1[4] = {l1a.x, l1a.y, l1b.x, l1b.y};
#pragma unroll
            for (int cg = 0; cg < 8; cg++) {
                const ulonglong2* wp = (const ulonglong2*)&ws[cc][cg8*8 + cg][0];
                ulonglong2 wa = wp[0], wb = wp[1];
#pragma unroll
                for (int q = 0; q < 4; q++) {
                    ffma2(acc[cg][q], wa.x, xh1[q]);
                    ffma2(acc[cg][q], wa.y, xh0[q]);
                    ffma2(acc[cg][q], wb.x, xl1[q]);
                    ffma2(acc[cg][q], wb.y, xl0[q]);
                }
            }
        }
        __syncthreads();
    }

    // epilogue: y = acc + b1 (stride-2 scatter into full-res y)
#pragma unroll
    for (int cg = 0; cg < 8; cg++) {
        int co = co0 + cg8*8 + cg;
        float bv = b1[co];
        int oh = 2*(R0 + r) + pr;
        float* dst = &g_y[((b*128 + co)*128 + oh)*128];
#pragma unroll
        for (int q = 0; q < 4; q++) {
            float lo, hi;
            unpack2(acc[cg][q], lo, hi);
            dst[2*(S0 + s8 + 2*q)     + ps] = lo + bv;
            dst[2*(S0 + s8 + 2*q + 1) + ps] = hi + bv;
        }
    }
}

// ---------------- stage 2a: gaussian kernel factors ----------------
__global__ __launch_bounds__(256)
void kfac_kernel(const float* CK guide) {
    const int tid = threadIdx.x;
    const int b = blockIdx.z;
    const int H0 = (blockIdx.x >> 3) * 16;
    const int W0 = (blockIdx.x & 7) * 16;
    __shared__ float gs[16][18][19];
    const int r  = tid >> 4;
    const int sc = tid & 15;
    float acc[9];
#pragma unroll
    for (int k = 0; k < 9; k++) acc[k] = 0.f;

    for (int ch = 0; ch < 8; ch++) {
        const int c0 = ch * 16;
        for (int e = tid; e < 16*18*18; e += 256) {
            int col = e % 18;
            int tmp = e / 18;
            int row = tmp % 18;
            int cc  = tmp / 18;
            int gr = H0 - 1 + row, gc = W0 - 1 + col;
            float v = 0.f;
            if ((unsigned)gr < 128u && (unsigned)gc < 128u)
                v = guide[((b*128 + c0 + cc)*128 + gr)*128 + gc];
            gs[cc][row][col] = v;
        }
        __syncthreads();
#pragma unroll 1
        for (int cc = 0; cc < 16; cc++) {
            float gc0 = gs[cc][r + 1][sc + 1];
#pragma unroll
            for (int ij = 0; ij < 9; ij++) {
                int di = ij / 3, dj = ij % 3;
                float d = gs[cc][r + di][sc + dj] - gc0;
                acc[ij] += d * d;
            }
        }
        __syncthreads();
    }
#pragma unroll
    for (int ij = 0; ij < 9; ij++)
        g_kf[((b*9 + ij)*128 + H0 + r)*128 + W0 + sc] = expf(-0.5f * acc[ij]);
}

// ---------------- stage 2b: PAC main (9-tap scaled conv, f32x2, LDS.128) ----------------
// Block: 64 co x (16x16) spatial tile. Thread: 8co x 8pos (4 f32x2 pairs).
// Three y copies (shift 0/1/2), row stride 20 floats (80B = 5x16B, odd slot
// stride -> LDS.128 conflict-free with lane map r=pg&15).
static const int PC_Y_STRIDE = 20;
static const int PC_YC_BYTES = 8*18*PC_Y_STRIDE*4;   // 5760 per copy
static const int PC_KS_BYTES = 9*16*PC_Y_STRIDE*4;   // 11520
static const int PC_WS_BYTES = 8*9*64*8;             // 36864 (ull pairs)
static const int PC_SMEM     = 3*PC_YC_BYTES + PC_KS_BYTES + PC_WS_BYTES;  // 65664

__global__ __launch_bounds__(256, 2)
void pac_kernel(const float* CK b2, float* CK out) {
    extern __shared__ unsigned char smem_raw[];
    float* ybase0 = (float*)smem_raw;                         // shift 0
    float* ybase1 = (float*)(smem_raw + PC_YC_BYTES);         // shift 1
    float* ybase2 = (float*)(smem_raw + 2*PC_YC_BYTES);       // shift 2
    float (*ksm)[16][PC_Y_STRIDE] =
        (float(*)[16][PC_Y_STRIDE])(smem_raw + 3*PC_YC_BYTES);
    ull   (*wsm)[9][64] = (ull(*)[9][64])(smem_raw + 3*PC_YC_BYTES + PC_KS_BYTES);

    const int tid = threadIdx.x;
    const int b = blockIdx.z;
    const int co0 = blockIdx.y * 64;
    const int H0 = (blockIdx.x >> 3) * 16;
    const int W0 = (blockIdx.x & 7) * 16;

    const int cg8 = tid >> 5;
    const int pg  = tid & 31;
    const int r   = pg & 15;           // 0..15 (phase-group friendly)
    const int sc8 = (pg >> 4) * 8;     // 0,8

    // gaussian factors for tile (once)
    for (int e = tid; e < 9*256; e += 256) {
        int cc = e & 255;
        int ij = e >> 8;
        int rr = cc >> 4, col = cc & 15;
        ksm[ij][rr][col] = g_kf[((b*9 + ij)*128 + H0 + rr)*128 + W0 + col];
    }

    ull acc[8][4];
#pragma unroll
    for (int a = 0; a < 8; a++)
#pragma unroll
        for (int q = 0; q < 4; q++) acc[a][q] = 0ull;

    for (int ch = 0; ch < 16; ch++) {
        const int c0 = ch * 8;
        // y halo tile; triple store: shift 0 / 1 / 2
        for (int e = tid; e < 8*18*18; e += 256) {
            int col = e % 18;
            int tmp = e / 18;
            int row = tmp % 18;
            int cc  = tmp / 18;
            int gr = H0 - 1 + row, gc = W0 - 1 + col;
            float v = 0.f;
            if ((unsigned)gr < 128u && (unsigned)gc < 128u)
                v = g_y[((b*128 + c0 + cc)*128 + gr)*128 + gc];
            int base = (cc*18 + row) * PC_Y_STRIDE;
            ybase0[base + col] = v;
            if (col >= 1) ybase1[base + col - 1] = v;
            if (col >= 2) ybase2[base + col - 2] = v;
        }
        // duplicated weight pairs
        {
            const ull* wsrc = ((const ull*)g_w2d) + (size_t)(c0*9)*128 + co0;
            for (int e = tid; e < 8*9*64; e += 256) {
                int ol = e & 63;
                int ij = (e >> 6) % 9;
                int cc = e / (9*64);
                wsm[cc][ij][ol] = wsrc[((size_t)cc*9 + ij)*128 + ol];
            }
        }
        __syncthreads();

#pragma unroll 1
        for (int ij = 0; ij < 9; ij++) {
            const int di = ij / 3, dj = ij % 3;
            const float* ysel = (dj == 0) ? ybase0 : (dj == 1) ? ybase1 : ybase2;
            const ulonglong2* kp = (const ulonglong2*)&ksm[ij][r][sc8];
            ulonglong2 k01 = kp[0], k23 = kp[1];
#pragma unroll
            for (int cc = 0; cc < 8; cc++) {
                const ulonglong2* yp =
                    (const ulonglong2*)(ysel + (cc*18 + r + di)*PC_Y_STRIDE + sc8);
                ulonglong2 ya = yp[0], yb = yp[1];
                ull t0 = mul2(ya.x, k01.x);
                ull t1 = mul2(ya.y, k01.y);
                ull t2 = mul2(yb.x, k23.x);
                ull t3 = mul2(yb.y, k23.y);
                const ulonglong2* wp = (const ulonglong2*)&wsm[cc][ij][cg8*8];
                ulonglong2 w01 = wp[0], w23 = wp[1], w45 = wp[2], w67 = wp[3];
                ffma2(acc[0][0], w01.x, t0); ffma2(acc[0][1], w01.x, t1);
                ffma2(acc[0][2], w01.x, t2); ffma2(acc[0][3], w01.x, t3);
                ffma2(acc[1][0], w01.y, t0); ffma2(acc[1][1], w01.y, t1);
                ffma2(acc[1][2], w01.y, t2); ffma2(acc[1][3], w01.y, t3);
                ffma2(acc[2][0], w23.x, t0); ffma2(acc[2][1], w23.x, t1);
                ffma2(acc[2][2], w23.x, t2); ffma2(acc[2][3], w23.x, t3);
                ffma2(acc[3][0], w23.y, t0); ffma2(acc[3][1], w23.y, t1);
                ffma2(acc[3][2], w23.y, t2); ffma2(acc[3][3], w23.y, t3);
                ffma2(acc[4][0], w45.x, t0); ffma2(acc[4][1], w45.x, t1);
                ffma2(acc[4][2], w45.x, t2); ffma2(acc[4][3], w45.x, t3);
                ffma2(acc[5][0], w45.y, t0); ffma2(acc[5][1], w45.y, t1);
                ffma2(acc[5][2], w45.y, t2); ffma2(acc[5][3], w45.y, t3);
                ffma2(acc[6][0], w67.x, t0); ffma2(acc[6][1], w67.x, t1);
                ffma2(acc[6][2], w67.x, t2); ffma2(acc[6][3], w67.x, t3);
                ffma2(acc[7][0], w67.y, t0); ffma2(acc[7][1], w67.y, t1);
                ffma2(acc[7][2], w67.y, t2); ffma2(acc[7][3], w67.y, t3);
            }
        }
        __syncthreads();
    }

    // epilogue: out = acc + b2 (STG.64 pairs)
#pragma unroll
    for (int cg = 0; cg < 8; cg++) {
        int co = co0 + cg8*8 + cg;
        float bv = b2[co];
        ull bvd = pack2(bv, bv);
        float* dst = &out[((size_t)(b*128 + co)*128 + H0 + r)*128 + W0 + sc8];
#pragma unroll
        for (int q = 0; q < 4; q++)
            *(ull*)(dst + 2*q) = add2(acc[cg][q], bvd);
    }
}

// ---------------- launch ----------------
extern "C" void kernel_launch(void* const* d_in, const int* in_sizes, int n_in,
                              void* d_out, int out_size) {
    const float* x     = (const float*)d_in[0];
    const float* guide = (const float*)d_in[1];
    const float* w1    = (const float*)d_in[2];
    const float* b1    = (const float*)d_in[3];
    const float* w2    = (const float*)d_in[4];
    const float* b2    = (const float*)d_in[5];
    float* out = (float*)d_out;

    cudaFuncSetAttribute(deconv_kernel, cudaFuncAttributeMaxDynamicSharedMemorySize, DC_SMEM);
    cudaFuncSetAttribute(pac_kernel,    cudaFuncAttributeMaxDynamicSharedMemorySize, PC_SMEM);

    prep_weights_kernel<<<(4*256*128*4 + 255)/256, 256>>>(w1, w2);
    deconv_kernel<<<dim3(16, 8, 4), 256, DC_SMEM>>>(x, b1);
    kfac_kernel<<<dim3(64, 1, 4), 256>>>(guide);
    pac_kernel<<<dim3(64, 2, 4), 256, PC_SMEM>>>(b2, out);
}